// round 1
// baseline (speedup 1.0000x reference)
#include <cuda_runtime.h>
#include <math.h>

#define B_   64
#define D_   128
#define N_   500000
#define KP1_ 4096

#define STH  512                 // score kernel threads
#define KPT  (KP1_ / STH)        // 8 k's per thread

// ---------------------------------------------------------------------------
// Score + softmax:  out[which][b][k] = softmax_k( dot(mem[idx[b][k]], x[b]) )
//   which==0: x=image, mem=memory_gene   -> out_image
//   which==1: x=gene,  mem=memory_image  -> out_gene
// One block per (b, which). Thread t owns k = t + j*STH (coalesced idx loads,
// coalesced output stores). 8 independent row-streams per thread => MLP~8.
// ---------------------------------------------------------------------------
__global__ __launch_bounds__(STH, 2)
void score_softmax_kernel(const float* __restrict__ image,
                          const float* __restrict__ gene,
                          const float* __restrict__ mem_image,
                          const float* __restrict__ mem_gene,
                          const int*   __restrict__ idx,
                          float*       __restrict__ out)
{
    const int b     = blockIdx.x;
    const int which = blockIdx.y;

    const float* x   = (which == 0 ? image    : gene)      + b * D_;
    const float* mem = (which == 0 ? mem_gene : mem_image);
    float*       op  = out + (size_t)which * (B_ * KP1_) + (size_t)b * KP1_;

    __shared__ float4 xs[D_ / 4];     // query row, broadcast
    __shared__ float  redm[16];       // per-warp partials
    __shared__ float  bval;           // broadcast slot

    const int t    = threadIdx.x;
    const int lane = t & 31;
    const int wid  = t >> 5;

    if (t < D_ / 4) xs[t] = reinterpret_cast<const float4*>(x)[t];
    __syncthreads();

    // Row base pointers for my 8 k's
    const int* idxrow = idx + (size_t)b * KP1_;
    const float4* rows[KPT];
#pragma unroll
    for (int j = 0; j < KPT; ++j) {
        int k = t + j * STH;
        rows[j] = reinterpret_cast<const float4*>(mem + (size_t)idxrow[k] * D_);
    }

    float acc[KPT];
#pragma unroll
    for (int j = 0; j < KPT; ++j) acc[j] = 0.0f;

#pragma unroll 4
    for (int d4 = 0; d4 < D_ / 4; ++d4) {
        float4 xv = xs[d4];
#pragma unroll
        for (int j = 0; j < KPT; ++j) {
            float4 r = rows[j][d4];
            acc[j] += r.x * xv.x + r.y * xv.y + r.z * xv.z + r.w * xv.w;
        }
    }

    // ---- block max ----
    float m = acc[0];
#pragma unroll
    for (int j = 1; j < KPT; ++j) m = fmaxf(m, acc[j]);
#pragma unroll
    for (int off = 16; off > 0; off >>= 1)
        m = fmaxf(m, __shfl_xor_sync(0xffffffffu, m, off));
    if (lane == 0) redm[wid] = m;
    __syncthreads();
    if (t < 16) {
        float mm = redm[t];
#pragma unroll
        for (int off = 8; off > 0; off >>= 1)
            mm = fmaxf(mm, __shfl_xor_sync(0x0000ffffu, mm, off));
        if (t == 0) bval = mm;
    }
    __syncthreads();
    const float rowmax = bval;
    __syncthreads();   // protect bval/redm reuse below

    // ---- exp + block sum ----
    float e[KPT];
    float s = 0.0f;
#pragma unroll
    for (int j = 0; j < KPT; ++j) {
        e[j] = expf(acc[j] - rowmax);
        s += e[j];
    }
#pragma unroll
    for (int off = 16; off > 0; off >>= 1)
        s += __shfl_xor_sync(0xffffffffu, s, off);
    if (lane == 0) redm[wid] = s;
    __syncthreads();
    if (t < 16) {
        float ss = redm[t];
#pragma unroll
        for (int off = 8; off > 0; off >>= 1)
            ss += __shfl_xor_sync(0x0000ffffu, ss, off);
        if (t == 0) bval = ss;
    }
    __syncthreads();
    const float inv = 1.0f / bval;

#pragma unroll
    for (int j = 0; j < KPT; ++j)
        op[t + j * STH] = e[j] * inv;   // coalesced
}

// ---------------------------------------------------------------------------
// Momentum update of the 64 positive rows, written into the OUTPUT copies.
//   pos = mem[index[b]]*0.5 + x[b]*0.5 ; pos /= ||pos||2 ; out_mem[index[b]] = pos
// which==0: mem_image/image -> new_mem_image region; which==1: gene.
// Reads the ORIGINAL bank (d_in), writes the copied bank (d_out).
// Duplicate indices: last b wins (matches .at[].set scatter order).
// ---------------------------------------------------------------------------
__global__ void momentum_update_kernel(const float* __restrict__ image,
                                       const float* __restrict__ gene,
                                       const float* __restrict__ mem_image,
                                       const float* __restrict__ mem_gene,
                                       const int*   __restrict__ index,
                                       float*       __restrict__ out)
{
    const int b     = blockIdx.x;
    const int which = blockIdx.y;
    const int myidx = index[b];

    // last-writer-wins: skip if a later batch element targets the same row
    for (int bp = b + 1; bp < B_; ++bp)
        if (index[bp] == myidx) return;

    const float* x   = (which == 0 ? image     : gene)     + b * D_;
    const float* mem = (which == 0 ? mem_image : mem_gene);
    float* dst = out + (size_t)2 * B_ * KP1_
                     + (size_t)which * N_ * D_
                     + (size_t)myidx * D_;

    const int t    = threadIdx.x;   // 128 threads = D_
    const int lane = t & 31;
    const int wid  = t >> 5;

    float v = mem[(size_t)myidx * D_ + t] * 0.5f + x[t] * 0.5f;

    __shared__ float ws[4];
    float s = v * v;
#pragma unroll
    for (int off = 16; off > 0; off >>= 1)
        s += __shfl_xor_sync(0xffffffffu, s, off);
    if (lane == 0) ws[wid] = s;
    __syncthreads();
    float total = ws[0] + ws[1] + ws[2] + ws[3];

    dst[t] = v * rsqrtf(total);
}

// ---------------------------------------------------------------------------
extern "C" void kernel_launch(void* const* d_in, const int* in_sizes, int n_in,
                              void* d_out, int out_size)
{
    const float* image     = (const float*)d_in[0];   // [64,128]
    const float* gene      = (const float*)d_in[1];   // [64,128]
    const float* mem_image = (const float*)d_in[2];   // [500000,128]
    const float* mem_gene  = (const float*)d_in[3];   // [500000,128]
    const int*   index     = (const int*)  d_in[4];   // [64]
    const int*   idx       = (const int*)  d_in[5];   // [64,4096]
    float*       out       = (float*)d_out;

    const size_t memElems = (size_t)N_ * D_;
    const size_t memBytes = memElems * sizeof(float);
    float* out_mem_image = out + (size_t)2 * B_ * KP1_;
    float* out_mem_gene  = out_mem_image + memElems;

    // 1) Bulk copies of the banks into the output (dominant, ~1 GB traffic)
    cudaMemcpyAsync(out_mem_image, mem_image, memBytes,
                    cudaMemcpyDeviceToDevice, 0);
    cudaMemcpyAsync(out_mem_gene,  mem_gene,  memBytes,
                    cudaMemcpyDeviceToDevice, 0);

    // 2) Gathered scores + softmax (independent of the copies)
    score_softmax_kernel<<<dim3(B_, 2), STH>>>(image, gene, mem_image,
                                               mem_gene, idx, out);

    // 3) Momentum scatter-update into the copied banks (after copies, same stream)
    momentum_update_kernel<<<dim3(B_, 2), D_>>>(image, gene, mem_image,
                                                mem_gene, index, out);
}